// round 8
// baseline (speedup 1.0000x reference)
#include <cuda_runtime.h>
#include <math.h>

#define SEQ     32768
#define HID     1024
#define THREADS 256
#define NWARP   (THREADS / 32)
#define MAXG    2048

// Scratch (no device allocation allowed). g_in/g_out are self-resetting:
// the barrier protocol leaves them zero at kernel exit, so every graph
// replay sees the same initial state (deterministic).
__device__ float    g_energies[SEQ];
__device__ float    g_bm[MAXG];
__device__ float    g_bs[MAXG];
__device__ unsigned g_in  = 0;
__device__ unsigned g_out = 0;

// min-blocks=8 forces regs<=32 so 8 blocks/SM are co-resident (1184 ceiling)
__global__ __launch_bounds__(THREADS, 8) void fused_attn_kernel(
    const float* __restrict__ hidden,
    const float* __restrict__ enc,
    float* __restrict__ out)
{
    __shared__ float4 sh_h[HID / 4];   // 4 KB
    __shared__ float  sh_m[NWARP], sh_s[NWARP];
    __shared__ float  sh_M, sh_inv;

    const int tid  = threadIdx.x;
    const int lane = tid & 31;
    const int warp = tid >> 5;
    const int G    = gridDim.x;        // power of two: pairs divide evenly

    sh_h[tid] = reinterpret_cast<const float4*>(hidden)[tid];
    __syncthreads();

    // ---------------- Phase 1: matvec + per-warp online softmax stats ----
    const int W  = G * NWARP;                  // total warps (power of two)
    const int gw = blockIdx.x * NWARP + warp;  // global warp id
    // exact balance: (SEQ/2) / W pairs per warp, no remainder

    float m_w = -INFINITY;   // lane 0 only (others carry junk, unused)
    float s_w = 0.0f;

    for (int r = gw * 2; r < SEQ; r += 2 * W) {
        const float4* p0 = reinterpret_cast<const float4*>(enc)
                         + (size_t)r * (HID / 4);
        const float4* p1 = p0 + (HID / 4);

        float a0 = 0.0f, a1 = 0.0f;
#pragma unroll
        for (int i = 0; i < 8; i++) {
            float4 x0 = __ldcs(p0 + i * 32 + lane);   // streaming, read-once
            float4 x1 = __ldcs(p1 + i * 32 + lane);
            float4 h  = sh_h[i * 32 + lane];
            a0 = fmaf(x0.x, h.x, a0); a0 = fmaf(x0.y, h.y, a0);
            a0 = fmaf(x0.z, h.z, a0); a0 = fmaf(x0.w, h.w, a0);
            a1 = fmaf(x1.x, h.x, a1); a1 = fmaf(x1.y, h.y, a1);
            a1 = fmaf(x1.z, h.z, a1); a1 = fmaf(x1.w, h.w, a1);
        }

#pragma unroll
        for (int o = 16; o; o >>= 1) {
            a0 += __shfl_xor_sync(0xffffffffu, a0, o);
            a1 += __shfl_xor_sync(0xffffffffu, a1, o);
        }

        if (lane == 0) {
            g_energies[r]     = a0;
            g_energies[r + 1] = a1;
            float mn = fmaxf(m_w, fmaxf(a0, a1));
            // m_w = -inf first time: expf(-inf)=0, 0*0=0 -> safe
            s_w = s_w * __expf(m_w - mn) + __expf(a0 - mn) + __expf(a1 - mn);
            m_w = mn;
        }
    }

    if (lane == 0) { sh_m[warp] = m_w; sh_s[warp] = s_w; }
    __syncthreads();

    // ---------------- Block combine + grid barrier -----------------------
    if (tid == 0) {
        float mb = -INFINITY;
#pragma unroll
        for (int i = 0; i < NWARP; i++) mb = fmaxf(mb, sh_m[i]);
        float sb = 0.0f;
#pragma unroll
        for (int i = 0; i < NWARP; i++) sb += sh_s[i] * __expf(sh_m[i] - mb);
        g_bm[blockIdx.x] = mb;
        g_bs[blockIdx.x] = sb;
        __threadfence();
        atomicAdd(&g_in, 1u);
        while (atomicAdd(&g_in, 0u) < (unsigned)G) { __nanosleep(64); }
        __threadfence();
    }
    __syncthreads();   // release the whole block once tid0 passes barrier

    // ---------------- Phase 2: combine block stats (redundant per block) -
    float m = -INFINITY;
    for (int i = tid; i < G; i += THREADS) m = fmaxf(m, g_bm[i]);
#pragma unroll
    for (int o = 16; o; o >>= 1)
        m = fmaxf(m, __shfl_xor_sync(0xffffffffu, m, o));
    if (lane == 0) sh_m[warp] = m;
    __syncthreads();
    if (tid == 0) {
        float M = -INFINITY;
#pragma unroll
        for (int i = 0; i < NWARP; i++) M = fmaxf(M, sh_m[i]);
        sh_M = M;
    }
    __syncthreads();
    const float M = sh_M;

    float s = 0.0f;
    for (int i = tid; i < G; i += THREADS)
        s += g_bs[i] * __expf(g_bm[i] - M);
#pragma unroll
    for (int o = 16; o; o >>= 1)
        s += __shfl_xor_sync(0xffffffffu, s, o);
    if (lane == 0) sh_s[warp] = s;
    __syncthreads();
    if (tid == 0) {
        float S = 0.0f;
#pragma unroll
        for (int i = 0; i < NWARP; i++) S += sh_s[i];
        sh_inv = 1.0f / S;
    }
    __syncthreads();
    const float inv = sh_inv;

    // ---------------- Phase 2b: write normalized outputs -----------------
    for (int i = blockIdx.x * THREADS + tid; i < SEQ; i += G * THREADS)
        out[i] = __expf(g_energies[i] - M) * inv;

    // ---------------- Exit protocol: self-reset barrier state ------------
    __syncthreads();
    if (tid == 0) {
        unsigned o = atomicAdd(&g_out, 1u);
        if (o == (unsigned)G - 1) {   // last block out: restore zeros
            g_in  = 0;
            g_out = 0;
            __threadfence();
        }
    }
}

// ---------------------------------------------------------------------------
extern "C" void kernel_launch(void* const* d_in, const int* in_sizes, int n_in,
                              void* d_out, int out_size)
{
    const float* hidden = (const float*)d_in[0];   // [1024]
    const float* enc    = (const float*)d_in[1];   // [32768, 1024]
    float* out          = (float*)d_out;           // [1,1,32768]

    // Power-of-two grid, sized under the co-residency ceiling so the grid
    // barrier is deadlock-free AND work divides exactly (zero imbalance).
    int sms = 148, nb = 0;
    cudaDeviceGetAttribute(&sms, cudaDevAttrMultiProcessorCount, 0);
    cudaOccupancyMaxActiveBlocksPerMultiprocessor(&nb, fused_attn_kernel,
                                                  THREADS, 0);
    if (nb < 1) nb = 1;
    int maxco = sms * nb;        // expect 148*8 = 1184
    int G = 1024;
    while (G > maxco) G >>= 1;   // safety fallback: 512, 256, ...
    if (G > MAXG) G = MAXG;

    fused_attn_kernel<<<G, THREADS>>>(hidden, enc, out);
}

// round 9
// speedup vs baseline: 1.0092x; 1.0092x over previous
#include <cuda_runtime.h>
#include <math.h>

#define SEQ     32768
#define HID     1024
#define THREADS 256
#define NWARP   (THREADS / 32)
#define MAXG    2048

// Scratch (no device allocation allowed). g_in/g_out are self-resetting:
// the barrier protocol leaves them zero at kernel exit, so every graph
// replay sees the same initial state (deterministic).
__device__ float    g_energies[SEQ];
__device__ float    g_bm[MAXG];
__device__ float    g_bs[MAXG];
__device__ unsigned g_in  = 0;
__device__ unsigned g_out = 0;

// min-blocks=8 forces regs<=32 so 8 blocks/SM are co-resident (1184 ceiling)
__global__ __launch_bounds__(THREADS, 8) void fused_attn_kernel(
    const float* __restrict__ hidden,
    const float* __restrict__ enc,
    float* __restrict__ out)
{
    __shared__ float4 sh_h[HID / 4];   // 4 KB
    __shared__ float  sh_m[NWARP], sh_s[NWARP];
    __shared__ float  sh_M, sh_inv;

    const int tid  = threadIdx.x;
    const int lane = tid & 31;
    const int warp = tid >> 5;
    const int G    = gridDim.x;        // power of two: pairs divide evenly

    sh_h[tid] = reinterpret_cast<const float4*>(hidden)[tid];
    __syncthreads();

    // ---------------- Phase 1: matvec + per-warp online softmax stats ----
    const int W  = G * NWARP;                  // total warps (power of two)
    const int gw = blockIdx.x * NWARP + warp;  // global warp id
    // exact balance: (SEQ/2) / W pairs per warp, no remainder

    float m_w = -INFINITY;   // lane 0 only (others carry junk, unused)
    float s_w = 0.0f;

    for (int r = gw * 2; r < SEQ; r += 2 * W) {
        const float4* p0 = reinterpret_cast<const float4*>(enc)
                         + (size_t)r * (HID / 4);
        const float4* p1 = p0 + (HID / 4);

        float a0 = 0.0f, a1 = 0.0f;
#pragma unroll
        for (int i = 0; i < 8; i++) {
            float4 x0 = __ldcs(p0 + i * 32 + lane);   // streaming, read-once
            float4 x1 = __ldcs(p1 + i * 32 + lane);
            float4 h  = sh_h[i * 32 + lane];
            a0 = fmaf(x0.x, h.x, a0); a0 = fmaf(x0.y, h.y, a0);
            a0 = fmaf(x0.z, h.z, a0); a0 = fmaf(x0.w, h.w, a0);
            a1 = fmaf(x1.x, h.x, a1); a1 = fmaf(x1.y, h.y, a1);
            a1 = fmaf(x1.z, h.z, a1); a1 = fmaf(x1.w, h.w, a1);
        }

#pragma unroll
        for (int o = 16; o; o >>= 1) {
            a0 += __shfl_xor_sync(0xffffffffu, a0, o);
            a1 += __shfl_xor_sync(0xffffffffu, a1, o);
        }

        if (lane == 0) {
            g_energies[r]     = a0;
            g_energies[r + 1] = a1;
            float mn = fmaxf(m_w, fmaxf(a0, a1));
            // m_w = -inf first time: expf(-inf)=0, 0*0=0 -> safe
            s_w = s_w * __expf(m_w - mn) + __expf(a0 - mn) + __expf(a1 - mn);
            m_w = mn;
        }
    }

    if (lane == 0) { sh_m[warp] = m_w; sh_s[warp] = s_w; }
    __syncthreads();

    // ---------------- Block combine + grid barrier -----------------------
    if (tid == 0) {
        float mb = -INFINITY;
#pragma unroll
        for (int i = 0; i < NWARP; i++) mb = fmaxf(mb, sh_m[i]);
        float sb = 0.0f;
#pragma unroll
        for (int i = 0; i < NWARP; i++) sb += sh_s[i] * __expf(sh_m[i] - mb);
        g_bm[blockIdx.x] = mb;
        g_bs[blockIdx.x] = sb;
        __threadfence();
        atomicAdd(&g_in, 1u);
        while (atomicAdd(&g_in, 0u) < (unsigned)G) { __nanosleep(64); }
        __threadfence();
    }
    __syncthreads();   // release the whole block once tid0 passes barrier

    // ---------------- Phase 2: combine block stats (redundant per block) -
    float m = -INFINITY;
    for (int i = tid; i < G; i += THREADS) m = fmaxf(m, g_bm[i]);
#pragma unroll
    for (int o = 16; o; o >>= 1)
        m = fmaxf(m, __shfl_xor_sync(0xffffffffu, m, o));
    if (lane == 0) sh_m[warp] = m;
    __syncthreads();
    if (tid == 0) {
        float M = -INFINITY;
#pragma unroll
        for (int i = 0; i < NWARP; i++) M = fmaxf(M, sh_m[i]);
        sh_M = M;
    }
    __syncthreads();
    const float M = sh_M;

    float s = 0.0f;
    for (int i = tid; i < G; i += THREADS)
        s += g_bs[i] * __expf(g_bm[i] - M);
#pragma unroll
    for (int o = 16; o; o >>= 1)
        s += __shfl_xor_sync(0xffffffffu, s, o);
    if (lane == 0) sh_s[warp] = s;
    __syncthreads();
    if (tid == 0) {
        float S = 0.0f;
#pragma unroll
        for (int i = 0; i < NWARP; i++) S += sh_s[i];
        sh_inv = 1.0f / S;
    }
    __syncthreads();
    const float inv = sh_inv;

    // ---------------- Phase 2b: write normalized outputs -----------------
    for (int i = blockIdx.x * THREADS + tid; i < SEQ; i += G * THREADS)
        out[i] = __expf(g_energies[i] - M) * inv;

    // ---------------- Exit protocol: self-reset barrier state ------------
    __syncthreads();
    if (tid == 0) {
        unsigned o = atomicAdd(&g_out, 1u);
        if (o == (unsigned)G - 1) {   // last block out: restore zeros
            g_in  = 0;
            g_out = 0;
            __threadfence();
        }
    }
}

// ---------------------------------------------------------------------------
extern "C" void kernel_launch(void* const* d_in, const int* in_sizes, int n_in,
                              void* d_out, int out_size)
{
    const float* hidden = (const float*)d_in[0];   // [1024]
    const float* enc    = (const float*)d_in[1];   // [32768, 1024]
    float* out          = (float*)d_out;           // [1,1,32768]

    // Power-of-two grid, sized under the co-residency ceiling so the grid
    // barrier is deadlock-free AND work divides exactly (zero imbalance).
    int sms = 148, nb = 0;
    cudaDeviceGetAttribute(&sms, cudaDevAttrMultiProcessorCount, 0);
    cudaOccupancyMaxActiveBlocksPerMultiprocessor(&nb, fused_attn_kernel,
                                                  THREADS, 0);
    if (nb < 1) nb = 1;
    int maxco = sms * nb;        // expect 148*8 = 1184
    int G = 1024;
    while (G > maxco) G >>= 1;   // safety fallback: 512, 256, ...
    if (G > MAXG) G = MAXG;

    fused_attn_kernel<<<G, THREADS>>>(hidden, enc, out);
}